// round 8
// baseline (speedup 1.0000x reference)
#include <cuda_runtime.h>
#include <cuda_bf16.h>
#include <cstdint>

#define NUM_REL_MAX   20000
#define NUM_EDGES_MAX 640000
#define DIM           128
#define NUM_HEAD      8
#define NEG_SLOPE     0.2f
#define SCAN_B        256
#define MAX_BLKS      ((NUM_REL_MAX + SCAN_B - 1) / SCAN_B)   // 79

// Scratch (device globals -- no allocation allowed)
__device__ float g_A[NUM_REL_MAX * DIM];           // emb @ W1^T + attn_bias
__device__ float g_B[NUM_REL_MAX * DIM];           // emb @ W2^T
__device__ float g_MSG[NUM_REL_MAX * DIM];         // emb @ aggr^T + aggr_bias
__device__ int   g_cnt[NUM_REL_MAX];               // edges per head
__device__ int   g_off[NUM_REL_MAX + 1];           // CSR offsets
__device__ int   g_pos[NUM_REL_MAX];               // running fill positions
__device__ int   g_blk[MAX_BLKS + 1];              // per-block sums / offsets
__device__ unsigned int g_rec[NUM_EDGES_MAX];      // packed (bin<<16)|tail
__device__ int   g_is64;                           // triplet dtype flag

__device__ __forceinline__ float leaky(float x) {
    return x >= 0.0f ? x : NEG_SLOPE * x;
}

// ---------------------------------------------------------------------------
// Detect triplet dtype + zero the histogram.
// ---------------------------------------------------------------------------
__global__ void detect_zero_kernel(const unsigned int* __restrict__ trip_w,
                                   int nwords, int M) {
    int gid = blockIdx.x * blockDim.x + threadIdx.x;
    for (int i = gid; i < M; i += gridDim.x * blockDim.x) g_cnt[i] = 0;
    if (blockIdx.x == 0) {
        __shared__ int any_nonzero;
        if (threadIdx.x == 0) any_nonzero = 0;
        __syncthreads();
        int i = 1 + 2 * threadIdx.x;   // odd 32-bit words
        if (i < nwords && i < 512) {
            if (trip_w[i] != 0u) atomicOr(&any_nonzero, 1);
        }
        __syncthreads();
        if (threadIdx.x == 0) g_is64 = any_nonzero ? 0 : 1;
    }
}

// ---------------------------------------------------------------------------
// Histogram of head indices (32-bit loads only; little-endian low word).
// ---------------------------------------------------------------------------
__global__ __launch_bounds__(256) void hist_kernel(const void* __restrict__ trip, int E) {
    const int* p = (const int*)trip;
    int stride = g_is64 ? 6 : 3;
    for (long e = blockIdx.x * blockDim.x + threadIdx.x; e < E;
         e += (long)gridDim.x * blockDim.x) {
        int h = p[e * stride];
        atomicAdd(&g_cnt[h], 1);
    }
}

// ---------------------------------------------------------------------------
// Hierarchical scan, stage 1: per-block (256-elem) exclusive scan.
// ---------------------------------------------------------------------------
__global__ __launch_bounds__(SCAN_B) void scan1_kernel(int M) {
    __shared__ int wsum[SCAN_B / 32];
    int tid = threadIdx.x;
    int lane = tid & 31;
    int wid = tid >> 5;
    int i = blockIdx.x * SCAN_B + tid;
    int v = (i < M) ? g_cnt[i] : 0;

    int x = v;
    #pragma unroll
    for (int s = 1; s < 32; s <<= 1) {
        int y = __shfl_up_sync(0xFFFFFFFFu, x, s);
        if (lane >= s) x += y;
    }
    if (lane == 31) wsum[wid] = x;
    __syncthreads();
    if (wid == 0) {
        int w = (lane < SCAN_B / 32) ? wsum[lane] : 0;
        #pragma unroll
        for (int s = 1; s < SCAN_B / 32; s <<= 1) {
            int y = __shfl_up_sync(0xFFFFFFFFu, w, s);
            if (lane >= s) w += y;
        }
        if (lane < SCAN_B / 32) wsum[lane] = w;
    }
    __syncthreads();
    int excl = x - v + (wid > 0 ? wsum[wid - 1] : 0);
    if (i < M) g_off[i] = excl;
    if (tid == SCAN_B - 1) g_blk[blockIdx.x] = excl + v;
}

// ---------------------------------------------------------------------------
// Stage 2: one warp scans block sums (nblk <= 96).
// ---------------------------------------------------------------------------
__global__ void scan2_kernel(int nblk, int M) {
    int lane = threadIdx.x;
    int vals[3];
    int total = 0;
    #pragma unroll
    for (int ch = 0; ch < 3; ch++) {
        int i = ch * 32 + lane;
        int v = (i < nblk) ? g_blk[i] : 0;
        int x = v;
        #pragma unroll
        for (int s = 1; s < 32; s <<= 1) {
            int y = __shfl_up_sync(0xFFFFFFFFu, x, s);
            if (lane >= s) x += y;
        }
        vals[ch] = x - v + total;
        total += __shfl_sync(0xFFFFFFFFu, x, 31);
    }
    #pragma unroll
    for (int ch = 0; ch < 3; ch++) {
        int i = ch * 32 + lane;
        if (i < nblk) g_blk[i] = vals[ch];
    }
    if (lane == 0) g_off[M] = total;
}

// ---------------------------------------------------------------------------
// Stage 3: add block offsets; copy to g_pos.
// ---------------------------------------------------------------------------
__global__ __launch_bounds__(SCAN_B) void scan3_kernel(int M) {
    int i = blockIdx.x * SCAN_B + threadIdx.x;
    if (i < M) {
        int o = g_off[i] + g_blk[blockIdx.x];
        g_off[i] = o;
        g_pos[i] = o;
    }
}

// ---------------------------------------------------------------------------
// Reorder edges into head-grouped records: rec = (bin<<16) | tail.
// ---------------------------------------------------------------------------
__global__ __launch_bounds__(256) void reorder_kernel(const void* __restrict__ trip, int E) {
    const int* p = (const int*)trip;
    int is64 = g_is64;
    int stride = is64 ? 6 : 3;
    int dt = is64 ? 2 : 1;
    int db = is64 ? 4 : 2;
    for (long e = blockIdx.x * blockDim.x + threadIdx.x; e < E;
         e += (long)gridDim.x * blockDim.x) {
        int h = p[e * stride];
        int t = p[e * stride + dt];
        int b = p[e * stride + db];
        int pos = atomicAdd(&g_pos[h], 1);
        g_rec[pos] = ((unsigned int)b << 16) | (unsigned int)t;
    }
}

// ---------------------------------------------------------------------------
// 3xTF32 tensor-core GEMM: P[M, 384] = emb[M,128] @ Wc[384,128]^T (+biases)
// Block tile 128x64, 8 warps (4x2), warp tile 32x32, mma.m16n8k8.tf32.
// Error-compensated split (hi + lo) gives fp32-level accuracy.
//   blockIdx.y: 0,1 -> g_A cols 0/64;  2,3 -> g_B;  4,5 -> g_MSG
// ---------------------------------------------------------------------------
#define TBM 128
#define TBN 64
#define TKT 16
#define LDP (TKT + 4)   // padded stride 20: conflict-free fragment loads

__device__ __forceinline__ void split_tf32(float f, uint32_t& hi, uint32_t& lo) {
    uint32_t h;
    asm("cvt.rna.tf32.f32 %0, %1;" : "=r"(h) : "f"(f));
    float r = f - __uint_as_float(h);
    uint32_t l;
    asm("cvt.rna.tf32.f32 %0, %1;" : "=r"(l) : "f"(r));
    hi = h; lo = l;
}

__device__ __forceinline__ void mma_tf32(float* d, const uint32_t* a, const uint32_t* b) {
    asm volatile(
        "mma.sync.aligned.m16n8k8.row.col.f32.tf32.tf32.f32 "
        "{%0,%1,%2,%3}, {%4,%5,%6,%7}, {%8,%9}, {%0,%1,%2,%3};"
        : "+f"(d[0]), "+f"(d[1]), "+f"(d[2]), "+f"(d[3])
        : "r"(a[0]), "r"(a[1]), "r"(a[2]), "r"(a[3]), "r"(b[0]), "r"(b[1]));
}

__global__ __launch_bounds__(256) void gemm_tf32_kernel(
    const float* __restrict__ emb,
    const float* __restrict__ attn_w,   // [128, 256]
    const float* __restrict__ attn_b,   // [128]
    const float* __restrict__ aggr_w,   // [128, 128]
    const float* __restrict__ aggr_b,   // [128]
    int M)
{
    __shared__ float As[TBM][LDP];
    __shared__ float Ws[TBN][LDP];

    int tid = threadIdx.x;
    int wid = tid >> 5, lane = tid & 31;
    int m0 = blockIdx.x * TBM;
    int region = blockIdx.y >> 1;          // 0: A, 1: B, 2: MSG
    int c0 = (blockIdx.y & 1) * TBN;       // col offset within region

    int warpM = wid >> 1;                  // 0..3 -> m offset *32
    int warpN = wid & 1;                   // 0..1 -> n offset *32
    int groupID = lane >> 2;               // 0..7
    int tig = lane & 3;                    // 0..3

    float acc[2][4][4];
    #pragma unroll
    for (int mt = 0; mt < 2; mt++)
        #pragma unroll
        for (int nt = 0; nt < 4; nt++)
            #pragma unroll
            for (int r = 0; r < 4; r++)
                acc[mt][nt][r] = 0.f;

    for (int kt = 0; kt < DIM; kt += TKT) {
        // A tile: 128 rows x 16 k -> 512 float4, 2 per thread
        #pragma unroll
        for (int i = 0; i < 2; i++) {
            int idx = tid + i * 256;
            int row = idx >> 2;
            int kq  = (idx & 3) * 4;
            float4 val = make_float4(0.f, 0.f, 0.f, 0.f);
            int gr = m0 + row;
            if (gr < M) val = *(const float4*)(emb + (size_t)gr * DIM + kt + kq);
            As[row][kq + 0] = val.x; As[row][kq + 1] = val.y;
            As[row][kq + 2] = val.z; As[row][kq + 3] = val.w;
        }
        // W tile: 64 cols x 16 k -> 256 float4, 1 per thread
        {
            int col = tid >> 2;
            int kq  = (tid & 3) * 4;
            int gc = c0 + col;
            const float* wrow =
                (region == 0) ? attn_w + (size_t)gc * 256 :
                (region == 1) ? attn_w + (size_t)gc * 256 + 128 :
                                aggr_w + (size_t)gc * 128;
            float4 val = *(const float4*)(wrow + kt + kq);
            Ws[col][kq + 0] = val.x; Ws[col][kq + 1] = val.y;
            Ws[col][kq + 2] = val.z; Ws[col][kq + 3] = val.w;
        }
        __syncthreads();

        #pragma unroll
        for (int ks = 0; ks < TKT; ks += 8) {
            uint32_t ahi[2][4], alo[2][4];
            #pragma unroll
            for (int mt = 0; mt < 2; mt++) {
                int rbase = warpM * 32 + mt * 16;
                float f0 = As[rbase + groupID][ks + tig];
                float f1 = As[rbase + groupID + 8][ks + tig];
                float f2 = As[rbase + groupID][ks + tig + 4];
                float f3 = As[rbase + groupID + 8][ks + tig + 4];
                split_tf32(f0, ahi[mt][0], alo[mt][0]);
                split_tf32(f1, ahi[mt][1], alo[mt][1]);
                split_tf32(f2, ahi[mt][2], alo[mt][2]);
                split_tf32(f3, ahi[mt][3], alo[mt][3]);
            }
            uint32_t bhi[4][2], blo[4][2];
            #pragma unroll
            for (int nt = 0; nt < 4; nt++) {
                int nbase = warpN * 32 + nt * 8;
                float f0 = Ws[nbase + groupID][ks + tig];
                float f1 = Ws[nbase + groupID][ks + tig + 4];
                split_tf32(f0, bhi[nt][0], blo[nt][0]);
                split_tf32(f1, bhi[nt][1], blo[nt][1]);
            }
            #pragma unroll
            for (int mt = 0; mt < 2; mt++)
                #pragma unroll
                for (int nt = 0; nt < 4; nt++) {
                    mma_tf32(acc[mt][nt], ahi[mt], bhi[nt]);   // hi*hi
                    mma_tf32(acc[mt][nt], alo[mt], bhi[nt]);   // lo*hi
                    mma_tf32(acc[mt][nt], ahi[mt], blo[nt]);   // hi*lo
                }
        }
        __syncthreads();
    }

    // Store with bias, region-routed. c0/c1 are adjacent cols -> float2 stores.
    #pragma unroll
    for (int mt = 0; mt < 2; mt++) {
        #pragma unroll
        for (int rr = 0; rr < 2; rr++) {             // rr=0 -> c0,c1; rr=1 -> c2,c3
            int gr = m0 + warpM * 32 + mt * 16 + groupID + rr * 8;
            if (gr >= M) continue;
            #pragma unroll
            for (int nt = 0; nt < 4; nt++) {
                int gc = c0 + warpN * 32 + nt * 8 + tig * 2;   // within region [0,128)
                float v0 = acc[mt][nt][rr * 2 + 0];
                float v1 = acc[mt][nt][rr * 2 + 1];
                if (region == 0) {
                    v0 += attn_b[gc]; v1 += attn_b[gc + 1];
                    *(float2*)(g_A + (size_t)gr * DIM + gc) = make_float2(v0, v1);
                } else if (region == 1) {
                    *(float2*)(g_B + (size_t)gr * DIM + gc) = make_float2(v0, v1);
                } else {
                    v0 += aggr_b[gc]; v1 += aggr_b[gc + 1];
                    *(float2*)(g_MSG + (size_t)gr * DIM + gc) = make_float2(v0, v1);
                }
            }
        }
    }
}

// ---------------------------------------------------------------------------
// Fused per-relation aggregation: one warp per head relation.
// Chunked coalesced rec loads (1 LDG per 32 edges) + 1-deep pipeline on the
// B/MSG row gathers to keep L2 requests in flight.
// ---------------------------------------------------------------------------
__global__ __launch_bounds__(256) void fused_aggr_kernel(
    const float* __restrict__ attn_bin,   // [10, 8]
    const float* __restrict__ attn_vec,   // [128]
    float* __restrict__ out,
    int M)
{
    __shared__ float lbin[16 * NUM_HEAD];
    if (threadIdx.x < 10 * NUM_HEAD)
        lbin[threadIdx.x] = leaky(attn_bin[threadIdx.x]);
    __syncthreads();

    int warp = blockIdx.x * (blockDim.x >> 5) + (threadIdx.x >> 5);
    int lane = threadIdx.x & 31;
    if (warp >= M) return;
    int h = warp;

    int e0 = g_off[h];
    int n  = g_off[h + 1] - e0;

    const float4* Bv = (const float4*)g_B;
    const float4* Mv = (const float4*)g_MSG;

    float4 a = ((const float4*)g_A)[(size_t)h * 32 + lane];
    float4 v = ((const float4*)attn_vec)[lane];
    int k = lane >> 2;

    float4 acc = make_float4(0.f, 0.f, 0.f, 0.f);
    float ssum = 0.f;

    for (int base = 0; base < n; base += 32) {
        int cnt = min(32, n - base);
        unsigned int rl = (base + lane < n) ? __ldg(g_rec + e0 + base + lane) : 0u;

        unsigned int rec = __shfl_sync(0xFFFFFFFFu, rl, 0);
        int t0 = rec & 0xFFFFu;
        float4 bb = Bv[(size_t)t0 * 32 + lane];
        float4 m  = Mv[(size_t)t0 * 32 + lane];

        for (int j = 0; j < cnt; j++) {
            int bcur = rec >> 16;
            float4 bbc = bb;
            float4 mc  = m;
            if (j + 1 < cnt) {                        // prefetch next edge
                rec = __shfl_sync(0xFFFFFFFFu, rl, j + 1);
                int tn = rec & 0xFFFFu;
                bb = Bv[(size_t)tn * 32 + lane];
                m  = Mv[(size_t)tn * 32 + lane];
            }
            float s = leaky(a.x + bbc.x) * v.x
                    + leaky(a.y + bbc.y) * v.y
                    + leaky(a.z + bbc.z) * v.z
                    + leaky(a.w + bbc.w) * v.w;
            s += __shfl_xor_sync(0xFFFFFFFFu, s, 1);
            s += __shfl_xor_sync(0xFFFFFFFFu, s, 2);

            float val = __expf(s + lbin[bcur * NUM_HEAD + k]);

            acc.x += val * mc.x;
            acc.y += val * mc.y;
            acc.z += val * mc.z;
            acc.w += val * mc.w;
            ssum  += val;
        }
    }

    float inv = __frcp_rn(ssum + 1e-16f);
    ((float4*)out)[(size_t)h * 32 + lane] =
        make_float4(acc.x * inv, acc.y * inv, acc.z * inv, acc.w * inv);
}

// ---------------------------------------------------------------------------
extern "C" void kernel_launch(void* const* d_in, const int* in_sizes, int n_in,
                              void* d_out, int out_size)
{
    const float* emb      = (const float*)d_in[0];
    const void*  trip     = (const void*)d_in[1];
    const float* attn_w   = (const float*)d_in[2];
    const float* attn_b   = (const float*)d_in[3];
    const float* attn_bin = (const float*)d_in[4];
    const float* attn_vec = (const float*)d_in[5];
    const float* aggr_w   = (const float*)d_in[6];
    const float* aggr_b   = (const float*)d_in[7];
    float*       out      = (float*)d_out;

    int M = in_sizes[0] / DIM;        // 20000
    int E = in_sizes[1] / 3;          // 640000
    int nblk = (M + SCAN_B - 1) / SCAN_B;

    // One-time host-side stream/event setup (host objects, no device memory).
    static cudaStream_t s_gemm = nullptr;
    static cudaEvent_t ev_fork = nullptr, ev_join = nullptr;
    if (s_gemm == nullptr) {
        cudaStreamCreateWithFlags(&s_gemm, cudaStreamNonBlocking);
        cudaEventCreateWithFlags(&ev_fork, cudaEventDisableTiming);
        cudaEventCreateWithFlags(&ev_join, cudaEventDisableTiming);
    }

    // Fork: GEMM (independent of edge indexing) on the side stream.
    cudaEventRecord(ev_fork, 0);
    cudaStreamWaitEvent(s_gemm, ev_fork, 0);

    dim3 ggrid((M + TBM - 1) / TBM, 6);
    gemm_tf32_kernel<<<ggrid, 256, 0, s_gemm>>>(emb, attn_w, attn_b, aggr_w, aggr_b, M);
    cudaEventRecord(ev_join, s_gemm);

    // Main stream: counting sort by head.
    detect_zero_kernel<<<80, 256>>>((const unsigned int*)trip, E * 3, M);
    hist_kernel<<<592, 256>>>(trip, E);
    scan1_kernel<<<nblk, SCAN_B>>>(M);
    scan2_kernel<<<1, 32>>>(nblk, M);
    scan3_kernel<<<nblk, SCAN_B>>>(M);
    reorder_kernel<<<592, 256>>>(trip, E);

    // Join: fused aggregation needs tables + sorted edges.
    cudaStreamWaitEvent(0, ev_join, 0);

    int warps_per_block = 256 / 32;
    int nblocks = (M + warps_per_block - 1) / warps_per_block;
    fused_aggr_kernel<<<nblocks, 256>>>(attn_bin, attn_vec, out, M);
}

// round 9
// speedup vs baseline: 1.2642x; 1.2642x over previous
#include <cuda_runtime.h>
#include <cuda_fp16.h>
#include <cstdint>

#define NUM_REL_MAX   20000
#define NUM_EDGES_MAX 640000
#define DIM           128
#define NUM_HEAD      8
#define NEG_SLOPE     0.2f
#define SCAN_B        256
#define MAX_BLKS      ((NUM_REL_MAX + SCAN_B - 1) / SCAN_B)   // 79

// Scratch (device globals -- no allocation allowed)
__device__ float  g_A[NUM_REL_MAX * DIM];          // emb @ W1^T + attn_bias (fp32)
__device__ __half g_Bh[NUM_REL_MAX * DIM];         // emb @ W2^T (fp16)
__device__ __half g_MSGh[NUM_REL_MAX * DIM];       // emb @ aggr^T + aggr_b (fp16)
__device__ int    g_cnt[NUM_REL_MAX];              // edges per head
__device__ int    g_off[NUM_REL_MAX + 1];          // CSR offsets
__device__ int    g_pos[NUM_REL_MAX];              // running fill positions
__device__ int    g_blk[MAX_BLKS + 1];             // per-block sums / offsets
__device__ unsigned int g_rec[NUM_EDGES_MAX];      // packed (bin<<16)|tail
__device__ int    g_is64;                          // triplet dtype flag

__device__ __forceinline__ float leaky(float x) {
    return x >= 0.0f ? x : NEG_SLOPE * x;
}

// ---------------------------------------------------------------------------
// Detect triplet dtype + zero the histogram.
// ---------------------------------------------------------------------------
__global__ void detect_zero_kernel(const unsigned int* __restrict__ trip_w,
                                   int nwords, int M) {
    int gid = blockIdx.x * blockDim.x + threadIdx.x;
    for (int i = gid; i < M; i += gridDim.x * blockDim.x) g_cnt[i] = 0;
    if (blockIdx.x == 0) {
        __shared__ int any_nonzero;
        if (threadIdx.x == 0) any_nonzero = 0;
        __syncthreads();
        int i = 1 + 2 * threadIdx.x;   // odd 32-bit words
        if (i < nwords && i < 512) {
            if (trip_w[i] != 0u) atomicOr(&any_nonzero, 1);
        }
        __syncthreads();
        if (threadIdx.x == 0) g_is64 = any_nonzero ? 0 : 1;
    }
}

// ---------------------------------------------------------------------------
// Histogram of head indices (32-bit loads only; little-endian low word).
// ---------------------------------------------------------------------------
__global__ __launch_bounds__(256) void hist_kernel(const void* __restrict__ trip, int E) {
    const int* p = (const int*)trip;
    int stride = g_is64 ? 6 : 3;
    for (long e = blockIdx.x * blockDim.x + threadIdx.x; e < E;
         e += (long)gridDim.x * blockDim.x) {
        int h = p[e * stride];
        atomicAdd(&g_cnt[h], 1);
    }
}

// ---------------------------------------------------------------------------
// Hierarchical scan, stage 1: per-block (256-elem) exclusive scan.
// ---------------------------------------------------------------------------
__global__ __launch_bounds__(SCAN_B) void scan1_kernel(int M) {
    __shared__ int wsum[SCAN_B / 32];
    int tid = threadIdx.x;
    int lane = tid & 31;
    int wid = tid >> 5;
    int i = blockIdx.x * SCAN_B + tid;
    int v = (i < M) ? g_cnt[i] : 0;

    int x = v;
    #pragma unroll
    for (int s = 1; s < 32; s <<= 1) {
        int y = __shfl_up_sync(0xFFFFFFFFu, x, s);
        if (lane >= s) x += y;
    }
    if (lane == 31) wsum[wid] = x;
    __syncthreads();
    if (wid == 0) {
        int w = (lane < SCAN_B / 32) ? wsum[lane] : 0;
        #pragma unroll
        for (int s = 1; s < SCAN_B / 32; s <<= 1) {
            int y = __shfl_up_sync(0xFFFFFFFFu, w, s);
            if (lane >= s) w += y;
        }
        if (lane < SCAN_B / 32) wsum[lane] = w;
    }
    __syncthreads();
    int excl = x - v + (wid > 0 ? wsum[wid - 1] : 0);
    if (i < M) g_off[i] = excl;
    if (tid == SCAN_B - 1) g_blk[blockIdx.x] = excl + v;
}

// ---------------------------------------------------------------------------
// Stage 2: one warp scans block sums (nblk <= 96).
// ---------------------------------------------------------------------------
__global__ void scan2_kernel(int nblk, int M) {
    int lane = threadIdx.x;
    int vals[3];
    int total = 0;
    #pragma unroll
    for (int ch = 0; ch < 3; ch++) {
        int i = ch * 32 + lane;
        int v = (i < nblk) ? g_blk[i] : 0;
        int x = v;
        #pragma unroll
        for (int s = 1; s < 32; s <<= 1) {
            int y = __shfl_up_sync(0xFFFFFFFFu, x, s);
            if (lane >= s) x += y;
        }
        vals[ch] = x - v + total;
        total += __shfl_sync(0xFFFFFFFFu, x, 31);
    }
    #pragma unroll
    for (int ch = 0; ch < 3; ch++) {
        int i = ch * 32 + lane;
        if (i < nblk) g_blk[i] = vals[ch];
    }
    if (lane == 0) g_off[M] = total;
}

// ---------------------------------------------------------------------------
// Stage 3: add block offsets; copy to g_pos.
// ---------------------------------------------------------------------------
__global__ __launch_bounds__(SCAN_B) void scan3_kernel(int M) {
    int i = blockIdx.x * SCAN_B + threadIdx.x;
    if (i < M) {
        int o = g_off[i] + g_blk[blockIdx.x];
        g_off[i] = o;
        g_pos[i] = o;
    }
}

// ---------------------------------------------------------------------------
// Reorder edges into head-grouped records: rec = (bin<<16) | tail.
// ---------------------------------------------------------------------------
__global__ __launch_bounds__(256) void reorder_kernel(const void* __restrict__ trip, int E) {
    const int* p = (const int*)trip;
    int is64 = g_is64;
    int stride = is64 ? 6 : 3;
    int dt = is64 ? 2 : 1;
    int db = is64 ? 4 : 2;
    for (long e = blockIdx.x * blockDim.x + threadIdx.x; e < E;
         e += (long)gridDim.x * blockDim.x) {
        int h = p[e * stride];
        int t = p[e * stride + dt];
        int b = p[e * stride + db];
        int pos = atomicAdd(&g_pos[h], 1);
        g_rec[pos] = ((unsigned int)b << 16) | (unsigned int)t;
    }
}

// ---------------------------------------------------------------------------
// Fused SGEMM (fp32 SIMT): P[M, 384] = emb[M,128] @ Wc[384,128]^T  (+biases)
//   cols [0,128)   -> g_A    fp32 (attn_w[c][0:128] + attn_b[c])
//   cols [128,256) -> g_Bh   fp16 (attn_w[c-128][128:256])
//   cols [256,384) -> g_MSGh fp16 (aggr_w[c-256] + aggr_b)
// ---------------------------------------------------------------------------
#define BM 64
#define BN 64

__global__ __launch_bounds__(256) void gemm_kernel(
    const float* __restrict__ emb,
    const float* __restrict__ attn_w,   // [128, 256]
    const float* __restrict__ attn_b,   // [128]
    const float* __restrict__ aggr_w,   // [128, 128]
    const float* __restrict__ aggr_b,   // [128]
    int M)
{
    __shared__ float As[DIM][BM];
    __shared__ float Ws[DIM][BN];

    int tid = threadIdx.x;
    int m0 = blockIdx.x * BM;
    int c0 = blockIdx.y * BN;

    #pragma unroll
    for (int i = 0; i < 8; i++) {
        int linear = tid + i * 256;
        int row = linear & 63;
        int c4  = linear >> 6;
        float4 v = make_float4(0.f, 0.f, 0.f, 0.f);
        int gr = m0 + row;
        if (gr < M) v = *(const float4*)(emb + (long)gr * DIM + c4 * 4);
        As[c4 * 4 + 0][row] = v.x;
        As[c4 * 4 + 1][row] = v.y;
        As[c4 * 4 + 2][row] = v.z;
        As[c4 * 4 + 3][row] = v.w;
    }
    #pragma unroll
    for (int i = 0; i < 8; i++) {
        int linear = tid + i * 256;
        int col = linear & 63;
        int c4  = linear >> 6;
        int gc = c0 + col;
        const float* wrow;
        if (gc < 128)      wrow = attn_w + (long)gc * 256;
        else if (gc < 256) wrow = attn_w + (long)(gc - 128) * 256 + 128;
        else               wrow = aggr_w + (long)(gc - 256) * 128;
        float4 v = *(const float4*)(wrow + c4 * 4);
        Ws[c4 * 4 + 0][col] = v.x;
        Ws[c4 * 4 + 1][col] = v.y;
        Ws[c4 * 4 + 2][col] = v.z;
        Ws[c4 * 4 + 3][col] = v.w;
    }
    __syncthreads();

    int ty = tid >> 4;
    int tx = tid & 15;
    float acc[4][4] = {};

    #pragma unroll 16
    for (int k = 0; k < DIM; k++) {
        float4 a = *(const float4*)&As[k][ty * 4];
        float4 w = *(const float4*)&Ws[k][tx * 4];
        float av[4] = {a.x, a.y, a.z, a.w};
        float wv[4] = {w.x, w.y, w.z, w.w};
        #pragma unroll
        for (int i = 0; i < 4; i++)
            #pragma unroll
            for (int j = 0; j < 4; j++)
                acc[i][j] += av[i] * wv[j];
    }

    #pragma unroll
    for (int i = 0; i < 4; i++) {
        int gr = m0 + ty * 4 + i;
        if (gr >= M) continue;
        #pragma unroll
        for (int j = 0; j < 4; j++) {
            int gc = c0 + tx * 4 + j;
            float val = acc[i][j];
            if (gc < 128) {
                g_A[(long)gr * DIM + gc] = val + attn_b[gc];
            } else if (gc < 256) {
                g_Bh[(long)gr * DIM + (gc - 128)] = __float2half(val);
            } else {
                g_MSGh[(long)gr * DIM + (gc - 256)] =
                    __float2half(val + aggr_b[gc - 256]);
            }
        }
    }
}

// ---------------------------------------------------------------------------
// Fused per-relation aggregation: one warp per head relation.
// B/MSG tables in fp16 (half traffic); rec prefetched one edge ahead.
// ---------------------------------------------------------------------------
__global__ __launch_bounds__(256) void fused_aggr_kernel(
    const float* __restrict__ attn_bin,   // [10, 8]
    const float* __restrict__ attn_vec,   // [128]
    float* __restrict__ out,
    int M)
{
    __shared__ float lbin[16 * NUM_HEAD];
    if (threadIdx.x < 10 * NUM_HEAD)
        lbin[threadIdx.x] = leaky(attn_bin[threadIdx.x]);
    __syncthreads();

    int warp = blockIdx.x * (blockDim.x >> 5) + (threadIdx.x >> 5);
    int lane = threadIdx.x & 31;
    if (warp >= M) return;
    int h = warp;

    int e0 = g_off[h];
    int e1 = g_off[h + 1];

    float4 a = *(const float4*)(g_A + (long)h * DIM + lane * 4);
    float4 v = *(const float4*)(attn_vec + lane * 4);
    int k = lane >> 2;

    const uint2* Bv = (const uint2*)g_Bh;     // 4 halves per lane
    const uint2* Mv = (const uint2*)g_MSGh;

    float4 acc = make_float4(0.f, 0.f, 0.f, 0.f);
    float ssum = 0.f;

    if (e0 < e1) {
        unsigned int rec = __ldg(g_rec + e0);
        for (int e = e0; e < e1; e++) {
            int t = rec & 0xFFFFu;
            int b = rec >> 16;
            if (e + 1 < e1) rec = __ldg(g_rec + e + 1);   // prefetch next

            uint2 braw = Bv[(size_t)t * 32 + lane];
            uint2 mraw = Mv[(size_t)t * 32 + lane];

            const __half2* bh = (const __half2*)&braw;
            const __half2* mh = (const __half2*)&mraw;
            float2 b01 = __half22float2(bh[0]);
            float2 b23 = __half22float2(bh[1]);
            float2 m01 = __half22float2(mh[0]);
            float2 m23 = __half22float2(mh[1]);

            float s = leaky(a.x + b01.x) * v.x
                    + leaky(a.y + b01.y) * v.y
                    + leaky(a.z + b23.x) * v.z
                    + leaky(a.w + b23.y) * v.w;
            s += __shfl_xor_sync(0xFFFFFFFFu, s, 1);
            s += __shfl_xor_sync(0xFFFFFFFFu, s, 2);

            float val = __expf(s + lbin[b * NUM_HEAD + k]);

            acc.x += val * m01.x;
            acc.y += val * m01.y;
            acc.z += val * m23.x;
            acc.w += val * m23.y;
            ssum  += val;
        }
    }

    float inv = __frcp_rn(ssum + 1e-16f);
    *(float4*)(out + (long)h * DIM + lane * 4) =
        make_float4(acc.x * inv, acc.y * inv, acc.z * inv, acc.w * inv);
}

// ---------------------------------------------------------------------------
extern "C" void kernel_launch(void* const* d_in, const int* in_sizes, int n_in,
                              void* d_out, int out_size)
{
    const float* emb      = (const float*)d_in[0];
    const void*  trip     = (const void*)d_in[1];
    const float* attn_w   = (const float*)d_in[2];
    const float* attn_b   = (const float*)d_in[3];
    const float* attn_bin = (const float*)d_in[4];
    const float* attn_vec = (const float*)d_in[5];
    const float* aggr_w   = (const float*)d_in[6];
    const float* aggr_b   = (const float*)d_in[7];
    float*       out      = (float*)d_out;

    int M = in_sizes[0] / DIM;        // 20000
    int E = in_sizes[1] / 3;          // 640000
    int nblk = (M + SCAN_B - 1) / SCAN_B;

    // One-time host-side stream/event setup (host objects, no device memory).
    static cudaStream_t s_gemm = nullptr;
    static cudaEvent_t ev_fork = nullptr, ev_join = nullptr;
    if (s_gemm == nullptr) {
        cudaStreamCreateWithFlags(&s_gemm, cudaStreamNonBlocking);
        cudaEventCreateWithFlags(&ev_fork, cudaEventDisableTiming);
        cudaEventCreateWithFlags(&ev_join, cudaEventDisableTiming);
    }

    // Fork: GEMM (independent of edge indexing) on the side stream.
    cudaEventRecord(ev_fork, 0);
    cudaStreamWaitEvent(s_gemm, ev_fork, 0);

    dim3 ggrid((M + BM - 1) / BM, (3 * DIM) / BN);
    gemm_kernel<<<ggrid, 256, 0, s_gemm>>>(emb, attn_w, attn_b, aggr_w, aggr_b, M);
    cudaEventRecord(ev_join, s_gemm);

    // Main stream: counting sort by head.
    detect_zero_kernel<<<80, 256>>>((const unsigned int*)trip, E * 3, M);
    hist_kernel<<<592, 256>>>(trip, E);
    scan1_kernel<<<nblk, SCAN_B>>>(M);
    scan2_kernel<<<1, 32>>>(nblk, M);
    scan3_kernel<<<nblk, SCAN_B>>>(M);
    reorder_kernel<<<592, 256>>>(trip, E);

    // Join: fused aggregation needs tables + sorted edges.
    cudaStreamWaitEvent(0, ev_join, 0);

    int warps_per_block = 256 / 32;
    int nblocks = (M + warps_per_block - 1) / warps_per_block;
    fused_aggr_kernel<<<nblocks, 256>>>(attn_bin, attn_vec, out, M);
}

// round 10
// speedup vs baseline: 1.3196x; 1.0438x over previous
#include <cuda_runtime.h>
#include <cuda_fp16.h>
#include <cstdint>

#define NUM_REL_MAX   20000
#define NUM_EDGES_MAX 640000
#define DIM           128
#define NUM_HEAD      8
#define NEG_SLOPE     0.2f
#define SCAN_B        256
#define MAX_BLKS      ((NUM_REL_MAX + SCAN_B - 1) / SCAN_B)   // 79

// Scratch (device globals -- no allocation allowed)
__device__ float  g_A[NUM_REL_MAX * DIM];          // emb @ W1^T + attn_bias (fp32)
__device__ __half g_Bh[NUM_REL_MAX * DIM];         // emb @ W2^T (fp16)
__device__ __half g_MSGh[NUM_REL_MAX * DIM];       // emb @ aggr^T + aggr_b (fp16)
__device__ int    g_cnt[NUM_REL_MAX];              // edges per head
__device__ int    g_off[NUM_REL_MAX + 1];          // CSR offsets
__device__ int    g_pos[NUM_REL_MAX];              // running fill positions
__device__ int    g_blk[MAX_BLKS + 1];             // per-block sums / offsets
__device__ unsigned int g_rec[NUM_EDGES_MAX];      // packed (bin<<16)|tail
__device__ int    g_is64;                          // triplet dtype flag

__device__ __forceinline__ float leaky(float x) {
    return x >= 0.0f ? x : NEG_SLOPE * x;
}

// ---------------------------------------------------------------------------
// Detect triplet dtype + zero the histogram.
// ---------------------------------------------------------------------------
__global__ void detect_zero_kernel(const unsigned int* __restrict__ trip_w,
                                   int nwords, int M) {
    int gid = blockIdx.x * blockDim.x + threadIdx.x;
    for (int i = gid; i < M; i += gridDim.x * blockDim.x) g_cnt[i] = 0;
    if (blockIdx.x == 0) {
        __shared__ int any_nonzero;
        if (threadIdx.x == 0) any_nonzero = 0;
        __syncthreads();
        int i = 1 + 2 * threadIdx.x;   // odd 32-bit words
        if (i < nwords && i < 512) {
            if (trip_w[i] != 0u) atomicOr(&any_nonzero, 1);
        }
        __syncthreads();
        if (threadIdx.x == 0) g_is64 = any_nonzero ? 0 : 1;
    }
}

// ---------------------------------------------------------------------------
// Histogram of head indices (32-bit loads only; little-endian low word).
// ---------------------------------------------------------------------------
__global__ __launch_bounds__(256) void hist_kernel(const void* __restrict__ trip, int E) {
    const int* p = (const int*)trip;
    int stride = g_is64 ? 6 : 3;
    for (long e = blockIdx.x * blockDim.x + threadIdx.x; e < E;
         e += (long)gridDim.x * blockDim.x) {
        int h = p[e * stride];
        atomicAdd(&g_cnt[h], 1);
    }
}

// ---------------------------------------------------------------------------
// Hierarchical scan, stage 1: per-block (256-elem) exclusive scan.
// ---------------------------------------------------------------------------
__global__ __launch_bounds__(SCAN_B) void scan1_kernel(int M) {
    __shared__ int wsum[SCAN_B / 32];
    int tid = threadIdx.x;
    int lane = tid & 31;
    int wid = tid >> 5;
    int i = blockIdx.x * SCAN_B + tid;
    int v = (i < M) ? g_cnt[i] : 0;

    int x = v;
    #pragma unroll
    for (int s = 1; s < 32; s <<= 1) {
        int y = __shfl_up_sync(0xFFFFFFFFu, x, s);
        if (lane >= s) x += y;
    }
    if (lane == 31) wsum[wid] = x;
    __syncthreads();
    if (wid == 0) {
        int w = (lane < SCAN_B / 32) ? wsum[lane] : 0;
        #pragma unroll
        for (int s = 1; s < SCAN_B / 32; s <<= 1) {
            int y = __shfl_up_sync(0xFFFFFFFFu, w, s);
            if (lane >= s) w += y;
        }
        if (lane < SCAN_B / 32) wsum[lane] = w;
    }
    __syncthreads();
    int excl = x - v + (wid > 0 ? wsum[wid - 1] : 0);
    if (i < M) g_off[i] = excl;
    if (tid == SCAN_B - 1) g_blk[blockIdx.x] = excl + v;
}

// ---------------------------------------------------------------------------
// Stage 2: one warp scans block sums (nblk <= 96).
// ---------------------------------------------------------------------------
__global__ void scan2_kernel(int nblk, int M) {
    int lane = threadIdx.x;
    int vals[3];
    int total = 0;
    #pragma unroll
    for (int ch = 0; ch < 3; ch++) {
        int i = ch * 32 + lane;
        int v = (i < nblk) ? g_blk[i] : 0;
        int x = v;
        #pragma unroll
        for (int s = 1; s < 32; s <<= 1) {
            int y = __shfl_up_sync(0xFFFFFFFFu, x, s);
            if (lane >= s) x += y;
        }
        vals[ch] = x - v + total;
        total += __shfl_sync(0xFFFFFFFFu, x, 31);
    }
    #pragma unroll
    for (int ch = 0; ch < 3; ch++) {
        int i = ch * 32 + lane;
        if (i < nblk) g_blk[i] = vals[ch];
    }
    if (lane == 0) g_off[M] = total;
}

// ---------------------------------------------------------------------------
// Stage 3: add block offsets; copy to g_pos.
// ---------------------------------------------------------------------------
__global__ __launch_bounds__(SCAN_B) void scan3_kernel(int M) {
    int i = blockIdx.x * SCAN_B + threadIdx.x;
    if (i < M) {
        int o = g_off[i] + g_blk[blockIdx.x];
        g_off[i] = o;
        g_pos[i] = o;
    }
}

// ---------------------------------------------------------------------------
// Reorder edges into head-grouped records: rec = (bin<<16) | tail.
// ---------------------------------------------------------------------------
__global__ __launch_bounds__(256) void reorder_kernel(const void* __restrict__ trip, int E) {
    const int* p = (const int*)trip;
    int is64 = g_is64;
    int stride = is64 ? 6 : 3;
    int dt = is64 ? 2 : 1;
    int db = is64 ? 4 : 2;
    for (long e = blockIdx.x * blockDim.x + threadIdx.x; e < E;
         e += (long)gridDim.x * blockDim.x) {
        int h = p[e * stride];
        int t = p[e * stride + dt];
        int b = p[e * stride + db];
        int pos = atomicAdd(&g_pos[h], 1);
        g_rec[pos] = ((unsigned int)b << 16) | (unsigned int)t;
    }
}

// ---------------------------------------------------------------------------
// Fused SGEMM (fp32 SIMT): P[M, 384] = emb[M,128] @ Wc[384,128]^T  (+biases)
// ---------------------------------------------------------------------------
#define BM 64
#define BN 64

__global__ __launch_bounds__(256) void gemm_kernel(
    const float* __restrict__ emb,
    const float* __restrict__ attn_w,   // [128, 256]
    const float* __restrict__ attn_b,   // [128]
    const float* __restrict__ aggr_w,   // [128, 128]
    const float* __restrict__ aggr_b,   // [128]
    int M)
{
    __shared__ float As[DIM][BM];
    __shared__ float Ws[DIM][BN];

    int tid = threadIdx.x;
    int m0 = blockIdx.x * BM;
    int c0 = blockIdx.y * BN;

    #pragma unroll
    for (int i = 0; i < 8; i++) {
        int linear = tid + i * 256;
        int row = linear & 63;
        int c4  = linear >> 6;
        float4 v = make_float4(0.f, 0.f, 0.f, 0.f);
        int gr = m0 + row;
        if (gr < M) v = *(const float4*)(emb + (long)gr * DIM + c4 * 4);
        As[c4 * 4 + 0][row] = v.x;
        As[c4 * 4 + 1][row] = v.y;
        As[c4 * 4 + 2][row] = v.z;
        As[c4 * 4 + 3][row] = v.w;
    }
    #pragma unroll
    for (int i = 0; i < 8; i++) {
        int linear = tid + i * 256;
        int col = linear & 63;
        int c4  = linear >> 6;
        int gc = c0 + col;
        const float* wrow;
        if (gc < 128)      wrow = attn_w + (long)gc * 256;
        else if (gc < 256) wrow = attn_w + (long)(gc - 128) * 256 + 128;
        else               wrow = aggr_w + (long)(gc - 256) * 128;
        float4 v = *(const float4*)(wrow + c4 * 4);
        Ws[c4 * 4 + 0][col] = v.x;
        Ws[c4 * 4 + 1][col] = v.y;
        Ws[c4 * 4 + 2][col] = v.z;
        Ws[c4 * 4 + 3][col] = v.w;
    }
    __syncthreads();

    int ty = tid >> 4;
    int tx = tid & 15;
    float acc[4][4] = {};

    #pragma unroll 16
    for (int k = 0; k < DIM; k++) {
        float4 a = *(const float4*)&As[k][ty * 4];
        float4 w = *(const float4*)&Ws[k][tx * 4];
        float av[4] = {a.x, a.y, a.z, a.w};
        float wv[4] = {w.x, w.y, w.z, w.w};
        #pragma unroll
        for (int i = 0; i < 4; i++)
            #pragma unroll
            for (int j = 0; j < 4; j++)
                acc[i][j] += av[i] * wv[j];
    }

    #pragma unroll
    for (int i = 0; i < 4; i++) {
        int gr = m0 + ty * 4 + i;
        if (gr >= M) continue;
        #pragma unroll
        for (int j = 0; j < 4; j++) {
            int gc = c0 + tx * 4 + j;
            float val = acc[i][j];
            if (gc < 128) {
                g_A[(long)gr * DIM + gc] = val + attn_b[gc];
            } else if (gc < 256) {
                g_Bh[(long)gr * DIM + (gc - 128)] = __float2half(val);
            } else {
                g_MSGh[(long)gr * DIM + (gc - 256)] =
                    __float2half(val + aggr_b[gc - 256]);
            }
        }
    }
}

// ---------------------------------------------------------------------------
// Fused per-relation aggregation: one warp per head relation.
// 2-edge unroll: two independent dot/shfl/exp chains per iteration so the
// SHFL (~26cyc) and MUFU latencies of the pair overlap.
// ---------------------------------------------------------------------------
__global__ __launch_bounds__(256) void fused_aggr_kernel(
    const float* __restrict__ attn_bin,   // [10, 8]
    const float* __restrict__ attn_vec,   // [128]
    float* __restrict__ out,
    int M)
{
    __shared__ float lbin[16 * NUM_HEAD];
    if (threadIdx.x < 10 * NUM_HEAD)
        lbin[threadIdx.x] = leaky(attn_bin[threadIdx.x]);
    __syncthreads();

    int warp = blockIdx.x * (blockDim.x >> 5) + (threadIdx.x >> 5);
    int lane = threadIdx.x & 31;
    if (warp >= M) return;
    int h = warp;

    int e0 = g_off[h];
    int e1 = g_off[h + 1];
    int n  = e1 - e0;

    float4 a = *(const float4*)(g_A + (long)h * DIM + lane * 4);
    float4 v = *(const float4*)(attn_vec + lane * 4);
    int k = lane >> 2;

    const uint2* Bv = (const uint2*)g_Bh;     // 4 halves per lane
    const uint2* Mv = (const uint2*)g_MSGh;

    float4 acc = make_float4(0.f, 0.f, 0.f, 0.f);
    float ssum = 0.f;

    unsigned int rec0 = 0, rec1 = 0;
    if (n > 0) rec0 = __ldg(g_rec + e0);
    if (n > 1) rec1 = __ldg(g_rec + e0 + 1);

    int e = e0;
    while (e + 1 < e1) {
        int t0 = rec0 & 0xFFFFu, b0 = rec0 >> 16;
        int t1 = rec1 & 0xFFFFu, b1 = rec1 >> 16;
        if (e + 2 < e1) rec0 = __ldg(g_rec + e + 2);   // roll pair ahead
        if (e + 3 < e1) rec1 = __ldg(g_rec + e + 3);

        // independent gathers
        uint2 braw0 = Bv[(size_t)t0 * 32 + lane];
        uint2 mraw0 = Mv[(size_t)t0 * 32 + lane];
        uint2 braw1 = Bv[(size_t)t1 * 32 + lane];
        uint2 mraw1 = Mv[(size_t)t1 * 32 + lane];
        float lb0 = lbin[b0 * NUM_HEAD + k];
        float lb1 = lbin[b1 * NUM_HEAD + k];

        const __half2* bh0 = (const __half2*)&braw0;
        const __half2* mh0 = (const __half2*)&mraw0;
        const __half2* bh1 = (const __half2*)&braw1;
        const __half2* mh1 = (const __half2*)&mraw1;
        float2 b001 = __half22float2(bh0[0]);
        float2 b023 = __half22float2(bh0[1]);
        float2 m001 = __half22float2(mh0[0]);
        float2 m023 = __half22float2(mh0[1]);
        float2 b101 = __half22float2(bh1[0]);
        float2 b123 = __half22float2(bh1[1]);
        float2 m101 = __half22float2(mh1[0]);
        float2 m123 = __half22float2(mh1[1]);

        // two independent dot chains
        float s0 = leaky(a.x + b001.x) * v.x
                 + leaky(a.y + b001.y) * v.y
                 + leaky(a.z + b023.x) * v.z
                 + leaky(a.w + b023.y) * v.w;
        float s1 = leaky(a.x + b101.x) * v.x
                 + leaky(a.y + b101.y) * v.y
                 + leaky(a.z + b123.x) * v.z
                 + leaky(a.w + b123.y) * v.w;

        // interleaved shfl trees (latencies overlap)
        float r0 = __shfl_xor_sync(0xFFFFFFFFu, s0, 1);
        float r1 = __shfl_xor_sync(0xFFFFFFFFu, s1, 1);
        s0 += r0;
        s1 += r1;
        r0 = __shfl_xor_sync(0xFFFFFFFFu, s0, 2);
        r1 = __shfl_xor_sync(0xFFFFFFFFu, s1, 2);
        s0 += r0;
        s1 += r1;

        float val0 = __expf(s0 + lb0);
        float val1 = __expf(s1 + lb1);

        acc.x += val0 * m001.x;
        acc.y += val0 * m001.y;
        acc.z += val0 * m023.x;
        acc.w += val0 * m023.y;
        ssum  += val0;
        acc.x += val1 * m101.x;
        acc.y += val1 * m101.y;
        acc.z += val1 * m123.x;
        acc.w += val1 * m123.y;
        ssum  += val1;

        e += 2;
    }

    if (e < e1) {   // odd tail, edge in rec0
        int t = rec0 & 0xFFFFu, b = rec0 >> 16;
        uint2 braw = Bv[(size_t)t * 32 + lane];
        uint2 mraw = Mv[(size_t)t * 32 + lane];
        const __half2* bh = (const __half2*)&braw;
        const __half2* mh = (const __half2*)&mraw;
        float2 b01 = __half22float2(bh[0]);
        float2 b23 = __half22float2(bh[1]);
        float2 m01 = __half22float2(mh[0]);
        float2 m23 = __half22float2(mh[1]);

        float s = leaky(a.x + b01.x) * v.x
                + leaky(a.y + b01.y) * v.y
                + leaky(a.z + b23.x) * v.z
                + leaky(a.w + b23.y) * v.w;
        s += __shfl_xor_sync(0xFFFFFFFFu, s, 1);
        s += __shfl_xor_sync(0xFFFFFFFFu, s, 2);

        float val = __expf(s + lbin[b * NUM_HEAD + k]);
        acc.x += val * m01.x;
        acc.y += val * m01.y;
        acc.z += val * m23.x;
        acc.w += val * m23.y;
        ssum  += val;
    }

    float inv = __frcp_rn(ssum + 1e-16f);
    *(float4*)(out + (long)h * DIM + lane * 4) =
        make_float4(acc.x * inv, acc.y * inv, acc.z * inv, acc.w * inv);
}

// ---------------------------------------------------------------------------
extern "C" void kernel_launch(void* const* d_in, const int* in_sizes, int n_in,
                              void* d_out, int out_size)
{
    const float* emb      = (const float*)d_in[0];
    const void*  trip     = (const void*)d_in[1];
    const float* attn_w   = (const float*)d_in[2];
    const float* attn_b   = (const float*)d_in[3];
    const float* attn_bin = (const float*)d_in[4];
    const float* attn_vec = (const float*)d_in[5];
    const float* aggr_w   = (const float*)d_in[6];
    const float* aggr_b   = (const float*)d_in[7];
    float*       out      = (float*)d_out;

    int M = in_sizes[0] / DIM;        // 20000
    int E = in_sizes[1] / 3;          // 640000
    int nblk = (M + SCAN_B - 1) / SCAN_B;

    // One-time host-side stream/event setup (host objects, no device memory).
    static cudaStream_t s_gemm = nullptr;
    static cudaEvent_t ev_fork = nullptr, ev_join = nullptr;
    if (s_gemm == nullptr) {
        cudaStreamCreateWithFlags(&s_gemm, cudaStreamNonBlocking);
        cudaEventCreateWithFlags(&ev_fork, cudaEventDisableTiming);
        cudaEventCreateWithFlags(&ev_join, cudaEventDisableTiming);
    }

    // Fork: GEMM (independent of edge indexing) on the side stream.
    cudaEventRecord(ev_fork, 0);
    cudaStreamWaitEvent(s_gemm, ev_fork, 0);

    dim3 ggrid((M + BM - 1) / BM, (3 * DIM) / BN);
    gemm_kernel<<<ggrid, 256, 0, s_gemm>>>(emb, attn_w, attn_b, aggr_w, aggr_b, M);
    cudaEventRecord(ev_join, s_gemm);

    // Main stream: counting sort by head.
    detect_zero_kernel<<<80, 256>>>((const unsigned int*)trip, E * 3, M);
    hist_kernel<<<592, 256>>>(trip, E);
    scan1_kernel<<<nblk, SCAN_B>>>(M);
    scan2_kernel<<<1, 32>>>(nblk, M);
    scan3_kernel<<<nblk, SCAN_B>>>(M);
    reorder_kernel<<<592, 256>>>(trip, E);

    // Join: fused aggregation needs tables + sorted edges.
    cudaStreamWaitEvent(0, ev_join, 0);

    int warps_per_block = 256 / 32;
    int nblocks = (M + warps_per_block - 1) / warps_per_block;
    fused_aggr_kernel<<<nblocks, 256>>>(attn_bin, attn_vec, out, M);
}

// round 12
// speedup vs baseline: 1.3653x; 1.0346x over previous
#include <cuda_runtime.h>
#include <cuda_fp16.h>
#include <cstdint>

#define NUM_REL_MAX   20000
#define NUM_EDGES_MAX 640000
#define DIM           128
#define NUM_HEAD      8
#define NEG_SLOPE     0.2f
#define SCAN_B        256
#define MAX_BLKS      ((NUM_REL_MAX + SCAN_B - 1) / SCAN_B)   // 79

// Scratch (device globals -- no allocation allowed)
__device__ float  g_A[NUM_REL_MAX * DIM];          // emb @ W1^T + attn_bias (fp32)
// Interleaved fp16 table: per relation row of 256 halves (512 B).
// Quad q (= dim group d/4) at byte offset q*16: [B[4q..4q+3] | MSG[4q..4q+3]]
__device__ __half g_BM[NUM_REL_MAX * 2 * DIM];
__device__ int    g_cnt[NUM_REL_MAX];              // edges per head
__device__ int    g_off[NUM_REL_MAX + 1];          // CSR offsets
__device__ int    g_pos[NUM_REL_MAX];              // running fill positions
__device__ int    g_blk[MAX_BLKS + 1];             // per-block sums / offsets
__device__ unsigned int g_rec[NUM_EDGES_MAX];      // packed (bin<<16)|tail
__device__ int    g_is64;                          // triplet dtype flag

__device__ __forceinline__ float leaky(float x) {
    return x >= 0.0f ? x : NEG_SLOPE * x;
}

// ---------------------------------------------------------------------------
// Detect triplet dtype + zero the histogram.
// ---------------------------------------------------------------------------
__global__ void detect_zero_kernel(const unsigned int* __restrict__ trip_w,
                                   int nwords, int M) {
    int gid = blockIdx.x * blockDim.x + threadIdx.x;
    for (int i = gid; i < M; i += gridDim.x * blockDim.x) g_cnt[i] = 0;
    if (blockIdx.x == 0) {
        __shared__ int any_nonzero;
        if (threadIdx.x == 0) any_nonzero = 0;
        __syncthreads();
        int i = 1 + 2 * threadIdx.x;   // odd 32-bit words
        if (i < nwords && i < 512) {
            if (trip_w[i] != 0u) atomicOr(&any_nonzero, 1);
        }
        __syncthreads();
        if (threadIdx.x == 0) g_is64 = any_nonzero ? 0 : 1;
    }
}

// ---------------------------------------------------------------------------
// Histogram of head indices (32-bit loads only; little-endian low word).
// ---------------------------------------------------------------------------
__global__ __launch_bounds__(256) void hist_kernel(const void* __restrict__ trip, int E) {
    const int* p = (const int*)trip;
    int stride = g_is64 ? 6 : 3;
    for (long e = blockIdx.x * blockDim.x + threadIdx.x; e < E;
         e += (long)gridDim.x * blockDim.x) {
        int h = p[e * stride];
        atomicAdd(&g_cnt[h], 1);
    }
}

// ---------------------------------------------------------------------------
// Hierarchical scan, stage 1: per-block (256-elem) exclusive scan.
// ---------------------------------------------------------------------------
__global__ __launch_bounds__(SCAN_B) void scan1_kernel(int M) {
    __shared__ int wsum[SCAN_B / 32];
    int tid = threadIdx.x;
    int lane = tid & 31;
    int wid = tid >> 5;
    int i = blockIdx.x * SCAN_B + tid;
    int v = (i < M) ? g_cnt[i] : 0;

    int x = v;
    #pragma unroll
    for (int s = 1; s < 32; s <<= 1) {
        int y = __shfl_up_sync(0xFFFFFFFFu, x, s);
        if (lane >= s) x += y;
    }
    if (lane == 31) wsum[wid] = x;
    __syncthreads();
    if (wid == 0) {
        int w = (lane < SCAN_B / 32) ? wsum[lane] : 0;
        #pragma unroll
        for (int s = 1; s < SCAN_B / 32; s <<= 1) {
            int y = __shfl_up_sync(0xFFFFFFFFu, w, s);
            if (lane >= s) w += y;
        }
        if (lane < SCAN_B / 32) wsum[lane] = w;
    }
    __syncthreads();
    int excl = x - v + (wid > 0 ? wsum[wid - 1] : 0);
    if (i < M) g_off[i] = excl;
    if (tid == SCAN_B - 1) g_blk[blockIdx.x] = excl + v;
}

// ---------------------------------------------------------------------------
// Stage 2: one warp scans block sums (nblk <= 96).
// ---------------------------------------------------------------------------
__global__ void scan2_kernel(int nblk, int M) {
    int lane = threadIdx.x;
    int vals[3];
    int total = 0;
    #pragma unroll
    for (int ch = 0; ch < 3; ch++) {
        int i = ch * 32 + lane;
        int v = (i < nblk) ? g_blk[i] : 0;
        int x = v;
        #pragma unroll
        for (int s = 1; s < 32; s <<= 1) {
            int y = __shfl_up_sync(0xFFFFFFFFu, x, s);
            if (lane >= s) x += y;
        }
        vals[ch] = x - v + total;
        total += __shfl_sync(0xFFFFFFFFu, x, 31);
    }
    #pragma unroll
    for (int ch = 0; ch < 3; ch++) {
        int i = ch * 32 + lane;
        if (i < nblk) g_blk[i] = vals[ch];
    }
    if (lane == 0) g_off[M] = total;
}

// ---------------------------------------------------------------------------
// Stage 3: add block offsets; copy to g_pos.
// ---------------------------------------------------------------------------
__global__ __launch_bounds__(SCAN_B) void scan3_kernel(int M) {
    int i = blockIdx.x * SCAN_B + threadIdx.x;
    if (i < M) {
        int o = g_off[i] + g_blk[blockIdx.x];
        g_off[i] = o;
        g_pos[i] = o;
    }
}

// ---------------------------------------------------------------------------
// Reorder edges into head-grouped records: rec = (bin<<16) | tail.
// ---------------------------------------------------------------------------
__global__ __launch_bounds__(256) void reorder_kernel(const void* __restrict__ trip, int E) {
    const int* p = (const int*)trip;
    int is64 = g_is64;
    int stride = is64 ? 6 : 3;
    int dt = is64 ? 2 : 1;
    int db = is64 ? 4 : 2;
    for (long e = blockIdx.x * blockDim.x + threadIdx.x; e < E;
         e += (long)gridDim.x * blockDim.x) {
        int h = p[e * stride];
        int t = p[e * stride + dt];
        int b = p[e * stride + db];
        int pos = atomicAdd(&g_pos[h], 1);
        g_rec[pos] = ((unsigned int)b << 16) | (unsigned int)t;
    }
}

// ---------------------------------------------------------------------------
// Fused SGEMM (fp32 SIMT): P[M, 384] = emb[M,128] @ Wc[384,128]^T  (+biases)
//   cols [0,128)   -> g_A  fp32
//   cols [128,256) -> g_BM interleaved fp16 (B part)
//   cols [256,384) -> g_BM interleaved fp16 (MSG part, +aggr_b)
// ---------------------------------------------------------------------------
#define BM 64
#define BN 64

__global__ __launch_bounds__(256) void gemm_kernel(
    const float* __restrict__ emb,
    const float* __restrict__ attn_w,   // [128, 256]
    const float* __restrict__ attn_b,   // [128]
    const float* __restrict__ aggr_w,   // [128, 128]
    const float* __restrict__ aggr_b,   // [128]
    int M)
{
    __shared__ float As[DIM][BM];
    __shared__ float Ws[DIM][BN];

    int tid = threadIdx.x;
    int m0 = blockIdx.x * BM;
    int c0 = blockIdx.y * BN;

    #pragma unroll
    for (int i = 0; i < 8; i++) {
        int linear = tid + i * 256;
        int row = linear & 63;
        int c4  = linear >> 6;
        float4 v = make_float4(0.f, 0.f, 0.f, 0.f);
        int gr = m0 + row;
        if (gr < M) v = *(const float4*)(emb + (long)gr * DIM + c4 * 4);
        As[c4 * 4 + 0][row] = v.x;
        As[c4 * 4 + 1][row] = v.y;
        As[c4 * 4 + 2][row] = v.z;
        As[c4 * 4 + 3][row] = v.w;
    }
    #pragma unroll
    for (int i = 0; i < 8; i++) {
        int linear = tid + i * 256;
        int col = linear & 63;
        int c4  = linear >> 6;
        int gc = c0 + col;
        const float* wrow;
        if (gc < 128)      wrow = attn_w + (long)gc * 256;
        else if (gc < 256) wrow = attn_w + (long)(gc - 128) * 256 + 128;
        else               wrow = aggr_w + (long)(gc - 256) * 128;
        float4 v = *(const float4*)(wrow + c4 * 4);
        Ws[c4 * 4 + 0][col] = v.x;
        Ws[c4 * 4 + 1][col] = v.y;
        Ws[c4 * 4 + 2][col] = v.z;
        Ws[c4 * 4 + 3][col] = v.w;
    }
    __syncthreads();

    int ty = tid >> 4;
    int tx = tid & 15;
    float acc[4][4] = {};

    #pragma unroll 16
    for (int k = 0; k < DIM; k++) {
        float4 a = *(const float4*)&As[k][ty * 4];
        float4 w = *(const float4*)&Ws[k][tx * 4];
        float av[4] = {a.x, a.y, a.z, a.w};
        float wv[4] = {w.x, w.y, w.z, w.w};
        #pragma unroll
        for (int i = 0; i < 4; i++)
            #pragma unroll
            for (int j = 0; j < 4; j++)
                acc[i][j] += av[i] * wv[j];
    }

    #pragma unroll
    for (int i = 0; i < 4; i++) {
        int gr = m0 + ty * 4 + i;
        if (gr >= M) continue;
        #pragma unroll
        for (int j = 0; j < 4; j++) {
            int gc = c0 + tx * 4 + j;
            float val = acc[i][j];
            if (gc < 128) {
                g_A[(long)gr * DIM + gc] = val + attn_b[gc];
            } else if (gc < 256) {
                int d = gc - 128;
                // B dim d -> row gr, quad d>>2, slot d&3 (first half of quad)
                g_BM[(long)gr * 256 + (d >> 2) * 8 + (d & 3)] = __float2half(val);
            } else {
                int d = gc - 256;
                // MSG dim d -> second half of quad
                g_BM[(long)gr * 256 + (d >> 2) * 8 + 4 + (d & 3)] =
                    __float2half(val + aggr_b[d]);
            }
        }
    }
}

// ---------------------------------------------------------------------------
// Fused per-relation aggregation: one warp per head relation.
// One LDG.128 per edge per lane (interleaved B|MSG quad) + 4-edge unroll.
// ---------------------------------------------------------------------------
struct EdgeVals { float2 b01, b23, m01, m23; };

__device__ __forceinline__ EdgeVals unpack_bm(uint4 raw) {
    EdgeVals ev;
    const __half2* hp = (const __half2*)&raw;
    ev.b01 = __half22float2(hp[0]);
    ev.b23 = __half22float2(hp[1]);
    ev.m01 = __half22float2(hp[2]);
    ev.m23 = __half22float2(hp[3]);
    return ev;
}

__global__ __launch_bounds__(256) void fused_aggr_kernel(
    const float* __restrict__ attn_bin,   // [10, 8]
    const float* __restrict__ attn_vec,   // [128]
    float* __restrict__ out,
    int M)
{
    __shared__ float lbin[16 * NUM_HEAD];
    if (threadIdx.x < 10 * NUM_HEAD)
        lbin[threadIdx.x] = leaky(attn_bin[threadIdx.x]);
    __syncthreads();

    int warp = blockIdx.x * (blockDim.x >> 5) + (threadIdx.x >> 5);
    int lane = threadIdx.x & 31;
    if (warp >= M) return;
    int h = warp;

    int e0 = g_off[h];
    int e1 = g_off[h + 1];

    float4 a = *(const float4*)(g_A + (long)h * DIM + lane * 4);
    float4 v = *(const float4*)(attn_vec + lane * 4);
    int k = lane >> 2;

    const uint4* BMv = (const uint4*)g_BM;   // 32 quads per relation row

    float4 acc = make_float4(0.f, 0.f, 0.f, 0.f);
    float ssum = 0.f;

    unsigned int r0 = 0, r1 = 0, r2 = 0, r3 = 0;
    int n = e1 - e0;
    if (n > 0) r0 = __ldg(g_rec + e0);
    if (n > 1) r1 = __ldg(g_rec + e0 + 1);
    if (n > 2) r2 = __ldg(g_rec + e0 + 2);
    if (n > 3) r3 = __ldg(g_rec + e0 + 3);

    int e = e0;
    while (e + 3 < e1) {
        int t0 = r0 & 0xFFFFu, b0 = r0 >> 16;
        int t1 = r1 & 0xFFFFu, b1 = r1 >> 16;
        int t2 = r2 & 0xFFFFu, b2 = r2 >> 16;
        int t3 = r3 & 0xFFFFu, b3 = r3 >> 16;
        if (e + 4 < e1) r0 = __ldg(g_rec + e + 4);
        if (e + 5 < e1) r1 = __ldg(g_rec + e + 5);
        if (e + 6 < e1) r2 = __ldg(g_rec + e + 6);
        if (e + 7 < e1) r3 = __ldg(g_rec + e + 7);

        // 4 independent 16B gathers (MLP=4)
        uint4 raw0 = BMv[(size_t)t0 * 32 + lane];
        uint4 raw1 = BMv[(size_t)t1 * 32 + lane];
        uint4 raw2 = BMv[(size_t)t2 * 32 + lane];
        uint4 raw3 = BMv[(size_t)t3 * 32 + lane];
        float lb0 = lbin[b0 * NUM_HEAD + k];
        float lb1 = lbin[b1 * NUM_HEAD + k];
        float lb2 = lbin[b2 * NUM_HEAD + k];
        float lb3 = lbin[b3 * NUM_HEAD + k];

        EdgeVals ev0 = unpack_bm(raw0);
        EdgeVals ev1 = unpack_bm(raw1);
        EdgeVals ev2 = unpack_bm(raw2);
        EdgeVals ev3 = unpack_bm(raw3);

        float s0 = leaky(a.x + ev0.b01.x) * v.x + leaky(a.y + ev0.b01.y) * v.y
                 + leaky(a.z + ev0.b23.x) * v.z + leaky(a.w + ev0.b23.y) * v.w;
        float s1 = leaky(a.x + ev1.b01.x) * v.x + leaky(a.y + ev1.b01.y) * v.y
                 + leaky(a.z + ev1.b23.x) * v.z + leaky(a.w + ev1.b23.y) * v.w;
        float s2 = leaky(a.x + ev2.b01.x) * v.x + leaky(a.y + ev2.b01.y) * v.y
                 + leaky(a.z + ev2.b23.x) * v.z + leaky(a.w + ev2.b23.y) * v.w;
        float s3 = leaky(a.x + ev3.b01.x) * v.x + leaky(a.y + ev3.b01.y) * v.y
                 + leaky(a.z + ev3.b23.x) * v.z + leaky(a.w + ev3.b23.y) * v.w;

        // interleaved shfl reduction trees (latencies overlap)
        float q0 = __shfl_xor_sync(0xFFFFFFFFu, s0, 1);
        float q1 = __shfl_xor_sync(0xFFFFFFFFu, s1, 1);
        float q2 = __shfl_xor_sync(0xFFFFFFFFu, s2, 1);
        float q3 = __shfl_xor_sync(0xFFFFFFFFu, s3, 1);
        s0 += q0; s1 += q1; s2 += q2; s3 += q3;
        q0 = __shfl_xor_sync(0xFFFFFFFFu, s0, 2);
        q1 = __shfl_xor_sync(0xFFFFFFFFu, s1, 2);
        q2 = __shfl_xor_sync(0xFFFFFFFFu, s2, 2);
        q3 = __shfl_xor_sync(0xFFFFFFFFu, s3, 2);
        s0 += q0; s1 += q1; s2 += q2; s3 += q3;

        float val0 = __expf(s0 + lb0);
        float val1 = __expf(s1 + lb1);
        float val2 = __expf(s2 + lb2);
        float val3 = __expf(s3 + lb3);

        acc.x += val0 * ev0.m01.x; acc.y += val0 * ev0.m01.y;
        acc.z += val0 * ev0.m23.x; acc.w += val0 * ev0.m23.y; ssum += val0;
        acc.x += val1 * ev1.m01.x; acc.y += val1 * ev1.m01.y;
        acc.z += val1 * ev1.m23.x; acc.w += val1 * ev1.m23.y; ssum += val1;
        acc.x += val2 * ev2.m01.x; acc.y += val2 * ev2.m01.y;
        acc.z += val2 * ev2.m23.x; acc.w += val2 * ev2.m23.y; ssum += val2;
        acc.x += val3 * ev3.m01.x; acc.y += val3 * ev3.m01.y;
        acc.z += val3 * ev3.m23.x; acc.w += val3 * ev3.m23.y; ssum += val3;

        e += 4;
    }

    // tail (<4 edges), direct loads
    for (; e < e1; e++) {
        unsigned int rec = __ldg(g_rec + e);
        int t = rec & 0xFFFFu, b = rec >> 16;
        uint4 raw = BMv[(size_t)t * 32 + lane];
        EdgeVals ev = unpack_bm(raw);

        float s = leaky(a.x + ev.b01.x) * v.x + leaky(a.y + ev.b01.y) * v.y
                + leaky(a.z + ev.b23.x) * v.z + leaky(a.w + ev.b23.y) * v.w;
        s += __shfl_xor_sync(0xFFFFFFFFu, s, 1);
        s += __shfl_xor_sync(0xFFFFFFFFu, s, 2);

        float val = __expf(s + lbin[b * NUM_HEAD + k]);
        acc.x += val * ev.m01.x; acc.y += val * ev.m01.y;
        acc.z += val * ev.m23.x; acc.w += val * ev.m23.y; ssum += val;
    }

    float inv = __frcp_rn(ssum + 1e-16f);
    *(float4*)(out + (long)h * DIM + lane * 4) =
        make_float4(acc.x * inv, acc.y * inv, acc.z * inv, acc.w * inv);
}

// ---------------------------------------------------------------------------
extern "C" void kernel_launch(void* const* d_in, const int* in_sizes, int n_in,
                              void* d_out, int out_size)
{
    const float* emb      = (const float*)d_in[0];
    const void*  trip     = (const void*)d_in[1];
    const float* attn_w   = (const float*)d_in[2];
    const float* attn_b   = (const float*)d_in[3];
    const float* attn_bin = (const float*)d_in[4];
    const float* attn_vec = (const float*)d_in[5];
    const float* aggr_w   = (const float*)d_in[6];
    const float* aggr_b   = (const float*)d_in[7];
    float*       out      = (float*)d_out;

    int M = in_sizes[0] / DIM;        // 20000
    int E = in_sizes[1] / 3;          // 640000
    int nblk = (M + SCAN_B - 1) / SCAN_B;

    // One-time host-side stream/event setup (host objects, no device memory).
    static cudaStream_t s_gemm = nullptr;
    static cudaEvent_t ev_fork = nullptr, ev_join = nullptr;
    if (s_gemm == nullptr) {
        cudaStreamCreateWithFlags(&s_gemm, cudaStreamNonBlocking);
        cudaEventCreateWithFlags(&ev_fork, cudaEventDisableTiming);
        cudaEventCreateWithFlags(&ev_join, cudaEventDisableTiming);
    }

    // Fork: GEMM (independent of edge indexing) on the side stream.
    cudaEventRecord(ev_fork, 0);
    cudaStreamWaitEvent(s_gemm, ev_fork, 0);

    dim3 ggrid((M + BM - 1) / BM, (3 * DIM) / BN);
    gemm_kernel<<<ggrid, 256, 0, s_gemm>>>(emb, attn_w, attn_b, aggr_w, aggr_b, M);
    cudaEventRecord(ev_join, s_gemm);

    // Main stream: counting sort by head.
    detect_zero_kernel<<<80, 256>>>((const unsigned int*)trip, E * 3, M);
    hist_kernel<<<592, 256>>>(trip, E);
    scan1_kernel<<<nblk, SCAN_B>>>(M);
    scan2_kernel<<<1, 32>>>(nblk, M);
    scan3_kernel<<<nblk, SCAN_B>>>(M);
    reorder_kernel<<<592, 256>>>(trip, E);

    // Join: fused aggregation needs tables + sorted edges.
    cudaStreamWaitEvent(0, ev_join, 0);

    int warps_per_block = 256 / 32;
    int nblocks = (M + warps_per_block - 1) / warps_per_block;
    fused_aggr_kernel<<<nblocks, 256>>>(attn_bin, attn_vec, out, M);
}

// round 13
// speedup vs baseline: 1.7313x; 1.2681x over previous
#include <cuda_runtime.h>
#include <cuda_fp16.h>
#include <cstdint>

#define NUM_REL_MAX   20000
#define NUM_EDGES_MAX 640000
#define DIM           128
#define NUM_HEAD      8
#define NEG_SLOPE     0.2f
#define SCAN_B        256
#define MAX_BLKS      ((NUM_REL_MAX + SCAN_B - 1) / SCAN_B)   // 79

// Scratch (device globals -- no allocation allowed)
__device__ float  g_A[NUM_REL_MAX * DIM];          // emb @ W1^T + attn_bias (fp32)
// Interleaved fp16 table: per relation row of 256 halves (512 B).
// Quad q at byte offset q*16: [B[4q..4q+3] | MSG[4q..4q+3]]
__device__ __half g_BM[NUM_REL_MAX * 2 * DIM];
__device__ __half g_embH[NUM_REL_MAX * DIM];       // emb hi (fp16)
__device__ __half g_embL[NUM_REL_MAX * DIM];       // emb lo (fp16 residual)
__device__ __half g_WH[384 * DIM];                 // combined weights hi
__device__ __half g_WL[384 * DIM];                 // combined weights lo
__device__ int    g_cnt[NUM_REL_MAX];
__device__ int    g_off[NUM_REL_MAX + 1];
__device__ int    g_pos[NUM_REL_MAX];
__device__ int    g_blk[MAX_BLKS + 1];
__device__ unsigned int g_rec[NUM_EDGES_MAX];      // packed (bin<<16)|tail
__device__ int    g_is64;

__device__ __forceinline__ float leaky(float x) {
    return x >= 0.0f ? x : NEG_SLOPE * x;
}

// ---------------------------------------------------------------------------
// Detect triplet dtype + zero the histogram.
// ---------------------------------------------------------------------------
__global__ void detect_zero_kernel(const unsigned int* __restrict__ trip_w,
                                   int nwords, int M) {
    int gid = blockIdx.x * blockDim.x + threadIdx.x;
    for (int i = gid; i < M; i += gridDim.x * blockDim.x) g_cnt[i] = 0;
    if (blockIdx.x == 0) {
        __shared__ int any_nonzero;
        if (threadIdx.x == 0) any_nonzero = 0;
        __syncthreads();
        int i = 1 + 2 * threadIdx.x;
        if (i < nwords && i < 512) {
            if (trip_w[i] != 0u) atomicOr(&any_nonzero, 1);
        }
        __syncthreads();
        if (threadIdx.x == 0) g_is64 = any_nonzero ? 0 : 1;
    }
}

// ---------------------------------------------------------------------------
// hi/lo fp16 split of emb (once; GEMM mainloop then has no conversions).
// ---------------------------------------------------------------------------
__global__ __launch_bounds__(256) void conv_emb_kernel(const float* __restrict__ emb, int n) {
    for (int i = blockIdx.x * blockDim.x + threadIdx.x; i < n;
         i += gridDim.x * blockDim.x) {
        float x = emb[i];
        __half h = __float2half(x);
        g_embH[i] = h;
        g_embL[i] = __float2half(x - __half2float(h));
    }
}

// Combined weight matrix Wc[384][128] hi/lo:
//   rows [0,128)   = attn_w[r][0:128]
//   rows [128,256) = attn_w[r-128][128:256]
//   rows [256,384) = aggr_w[r-256]
__global__ __launch_bounds__(256) void conv_w_kernel(
    const float* __restrict__ attn_w, const float* __restrict__ aggr_w) {
    int idx = blockIdx.x * blockDim.x + threadIdx.x;
    if (idx >= 384 * DIM) return;
    int r = idx >> 7, c = idx & 127;
    float x = (r < 128)  ? attn_w[r * 256 + c]
            : (r < 256)  ? attn_w[(r - 128) * 256 + 128 + c]
                         : aggr_w[(r - 256) * 128 + c];
    __half h = __float2half(x);
    g_WH[idx] = h;
    g_WL[idx] = __float2half(x - __half2float(h));
}

// ---------------------------------------------------------------------------
// Histogram of head indices.
// ---------------------------------------------------------------------------
__global__ __launch_bounds__(256) void hist_kernel(const void* __restrict__ trip, int E) {
    const int* p = (const int*)trip;
    int stride = g_is64 ? 6 : 3;
    for (long e = blockIdx.x * blockDim.x + threadIdx.x; e < E;
         e += (long)gridDim.x * blockDim.x) {
        int h = p[e * stride];
        atomicAdd(&g_cnt[h], 1);
    }
}

// ---------------------------------------------------------------------------
// Hierarchical scan (3 stages).
// ---------------------------------------------------------------------------
__global__ __launch_bounds__(SCAN_B) void scan1_kernel(int M) {
    __shared__ int wsum[SCAN_B / 32];
    int tid = threadIdx.x;
    int lane = tid & 31;
    int wid = tid >> 5;
    int i = blockIdx.x * SCAN_B + tid;
    int v = (i < M) ? g_cnt[i] : 0;

    int x = v;
    #pragma unroll
    for (int s = 1; s < 32; s <<= 1) {
        int y = __shfl_up_sync(0xFFFFFFFFu, x, s);
        if (lane >= s) x += y;
    }
    if (lane == 31) wsum[wid] = x;
    __syncthreads();
    if (wid == 0) {
        int w = (lane < SCAN_B / 32) ? wsum[lane] : 0;
        #pragma unroll
        for (int s = 1; s < SCAN_B / 32; s <<= 1) {
            int y = __shfl_up_sync(0xFFFFFFFFu, w, s);
            if (lane >= s) w += y;
        }
        if (lane < SCAN_B / 32) wsum[lane] = w;
    }
    __syncthreads();
    int excl = x - v + (wid > 0 ? wsum[wid - 1] : 0);
    if (i < M) g_off[i] = excl;
    if (tid == SCAN_B - 1) g_blk[blockIdx.x] = excl + v;
}

__global__ void scan2_kernel(int nblk, int M) {
    int lane = threadIdx.x;
    int vals[3];
    int total = 0;
    #pragma unroll
    for (int ch = 0; ch < 3; ch++) {
        int i = ch * 32 + lane;
        int v = (i < nblk) ? g_blk[i] : 0;
        int x = v;
        #pragma unroll
        for (int s = 1; s < 32; s <<= 1) {
            int y = __shfl_up_sync(0xFFFFFFFFu, x, s);
            if (lane >= s) x += y;
        }
        vals[ch] = x - v + total;
        total += __shfl_sync(0xFFFFFFFFu, x, 31);
    }
    #pragma unroll
    for (int ch = 0; ch < 3; ch++) {
        int i = ch * 32 + lane;
        if (i < nblk) g_blk[i] = vals[ch];
    }
    if (lane == 0) g_off[M] = total;
}

__global__ __launch_bounds__(SCAN_B) void scan3_kernel(int M) {
    int i = blockIdx.x * SCAN_B + threadIdx.x;
    if (i < M) {
        int o = g_off[i] + g_blk[blockIdx.x];
        g_off[i] = o;
        g_pos[i] = o;
    }
}

// ---------------------------------------------------------------------------
// Reorder edges into head-grouped records.
// ---------------------------------------------------------------------------
__global__ __launch_bounds__(256) void reorder_kernel(const void* __restrict__ trip, int E) {
    const int* p = (const int*)trip;
    int is64 = g_is64;
    int stride = is64 ? 6 : 3;
    int dt = is64 ? 2 : 1;
    int db = is64 ? 4 : 2;
    for (long e = blockIdx.x * blockDim.x + threadIdx.x; e < E;
         e += (long)gridDim.x * blockDim.x) {
        int h = p[e * stride];
        int t = p[e * stride + dt];
        int b = p[e * stride + db];
        int pos = atomicAdd(&g_pos[h], 1);
        g_rec[pos] = ((unsigned int)b << 16) | (unsigned int)t;
    }
}

// ---------------------------------------------------------------------------
// HMMA GEMM (fp16 hi/lo, fp32 accum -> fp32 parity):
// P[M,384] = emb[M,128] @ Wc[384,128]^T (+biases)
// Block tile 128x64, 8 warps (4x2), warp tile 32x32, mma.m16n8k16.
//   blockIdx.y: 0,1 -> g_A ; 2,3 -> g_BM(B) ; 4,5 -> g_BM(MSG)
// ---------------------------------------------------------------------------
#define GBM 128
#define GBN 64
#define GKT 16

__device__ __forceinline__ void mma_f16(float* d, const uint32_t* a, const uint32_t* b) {
    asm volatile(
        "mma.sync.aligned.m16n8k16.row.col.f32.f16.f16.f32 "
        "{%0,%1,%2,%3}, {%4,%5,%6,%7}, {%8,%9}, {%0,%1,%2,%3};"
        : "+f"(d[0]), "+f"(d[1]), "+f"(d[2]), "+f"(d[3])
        : "r"(a[0]), "r"(a[1]), "r"(a[2]), "r"(a[3]), "r"(b[0]), "r"(b[1]));
}

__global__ __launch_bounds__(256) void gemm_hmma_kernel(
    const float* __restrict__ attn_b,   // [128]
    const float* __restrict__ aggr_b,   // [128]
    int M)
{
    __shared__ __half AsH[GBM][GKT];
    __shared__ __half AsL[GBM][GKT];
    __shared__ __half WsH[GBN][GKT];
    __shared__ __half WsL[GBN][GKT];

    int tid = threadIdx.x;
    int wid = tid >> 5, lane = tid & 31;
    int m0 = blockIdx.x * GBM;
    int region = blockIdx.y >> 1;          // 0: A, 1: B, 2: MSG
    int c0 = (blockIdx.y & 1) * GBN;       // col offset within region
    int wrow0 = region * DIM + c0;         // row base in combined Wc

    int warpM = wid >> 1;                  // 0..3
    int warpN = wid & 1;                   // 0..1
    int g = lane >> 2;                     // groupID 0..7
    int t = lane & 3;                      // 0..3

    float acc[2][4][4];
    #pragma unroll
    for (int mt = 0; mt < 2; mt++)
        #pragma unroll
        for (int nt = 0; nt < 4; nt++)
            #pragma unroll
            for (int r = 0; r < 4; r++) acc[mt][nt][r] = 0.f;

    for (int kt = 0; kt < DIM; kt += GKT) {
        // A tiles: 128x16 halves = 1024 u32 per table; 4 u32/thread each
        #pragma unroll
        for (int j = 0; j < 4; j++) {
            int idx = tid + j * 256;          // 0..1023
            int row = idx >> 3;
            int kc  = (idx & 7) * 2;          // even half index
            int gr = m0 + row;
            uint32_t vh = 0, vl = 0;
            if (gr < M) {
                vh = *(const uint32_t*)(g_embH + (size_t)gr * DIM + kt + kc);
                vl = *(const uint32_t*)(g_embL + (size_t)gr * DIM + kt + kc);
            }
            *(uint32_t*)&AsH[row][kc] = vh;
            *(uint32_t*)&AsL[row][kc] = vl;
        }
        // W tiles: 64x16 halves = 512 u32 per table; 2 u32/thread each
        #pragma unroll
        for (int j = 0; j < 2; j++) {
            int idx = tid + j * 256;          // 0..511
            int col = idx >> 3;
            int kc  = (idx & 7) * 2;
            uint32_t vh = *(const uint32_t*)(g_WH + (size_t)(wrow0 + col) * DIM + kt + kc);
            uint32_t vl = *(const uint32_t*)(g_WL + (size_t)(wrow0 + col) * DIM + kt + kc);
            *(uint32_t*)&WsH[col][kc] = vh;
            *(uint32_t*)&WsL[col][kc] = vl;
        }
        __syncthreads();

        uint32_t aH[2][4], aL[2][4];
        #pragma unroll
        for (int mt = 0; mt < 2; mt++) {
            int rb = warpM * 32 + mt * 16;
            aH[mt][0] = *(const uint32_t*)&AsH[rb + g][2 * t];
            aH[mt][1] = *(const uint32_t*)&AsH[rb + g + 8][2 * t];
            aH[mt][2] = *(const uint32_t*)&AsH[rb + g][2 * t + 8];
            aH[mt][3] = *(const uint32_t*)&AsH[rb + g + 8][2 * t + 8];
            aL[mt][0] = *(const uint32_t*)&AsL[rb + g][2 * t];
            aL[mt][1] = *(const uint32_t*)&AsL[rb + g + 8][2 * t];
            aL[mt][2] = *(const uint32_t*)&AsL[rb + g][2 * t + 8];
            aL[mt][3] = *(const uint32_t*)&AsL[rb + g + 8][2 * t + 8];
        }
        uint32_t bH[4][2], bL[4][2];
        #pragma unroll
        for (int nt = 0; nt < 4; nt++) {
            int nb = warpN * 32 + nt * 8;
            bH[nt][0] = *(const uint32_t*)&WsH[nb + g][2 * t];
            bH[nt][1] = *(const uint32_t*)&WsH[nb + g][2 * t + 8];
            bL[nt][0] = *(const uint32_t*)&WsL[nb + g][2 * t];
            bL[nt][1] = *(const uint32_t*)&WsL[nb + g][2 * t + 8];
        }
        #pragma unroll
        for (int mt = 0; mt < 2; mt++)
            #pragma unroll
            for (int nt = 0; nt < 4; nt++) {
                mma_f16(acc[mt][nt], aH[mt], bH[nt]);   // hi*hi
                mma_f16(acc[mt][nt], aL[mt], bH[nt]);   // lo*hi
                mma_f16(acc[mt][nt], aH[mt], bL[nt]);   // hi*lo
            }
        __syncthreads();
    }

    // Store, region-routed. c regs: {row g: c0,c1}, {row g+8: c2,c3}, cols 2t,2t+1.
    #pragma unroll
    for (int mt = 0; mt < 2; mt++) {
        #pragma unroll
        for (int rr = 0; rr < 2; rr++) {
            int gr = m0 + warpM * 32 + mt * 16 + g + rr * 8;
            if (gr >= M) continue;
            #pragma unroll
            for (int nt = 0; nt < 4; nt++) {
                int d = c0 + warpN * 32 + nt * 8 + t * 2;   // col within region [0,128)
                float v0 = acc[mt][nt][rr * 2 + 0];
                float v1 = acc[mt][nt][rr * 2 + 1];
                if (region == 0) {
                    g_A[(size_t)gr * DIM + d]     = v0 + attn_b[d];
                    g_A[(size_t)gr * DIM + d + 1] = v1 + attn_b[d + 1];
                } else if (region == 1) {
                    // B dim d -> quad d>>2, slot d&3 (first half of quad)
                    g_BM[(size_t)gr * 256 + (d >> 2) * 8 + (d & 3)]           = __float2half(v0);
                    g_BM[(size_t)gr * 256 + ((d + 1) >> 2) * 8 + ((d + 1) & 3)] = __float2half(v1);
                } else {
                    g_BM[(size_t)gr * 256 + (d >> 2) * 8 + 4 + (d & 3)] =
                        __float2half(v0 + aggr_b[d]);
                    g_BM[(size_t)gr * 256 + ((d + 1) >> 2) * 8 + 4 + ((d + 1) & 3)] =
                        __float2half(v1 + aggr_b[d + 1]);
                }
            }
        }
    }
}

// ---------------------------------------------------------------------------
// Fused per-relation aggregation (unchanged from R12).
// ---------------------------------------------------------------------------
struct EdgeVals { float2 b01, b23, m01, m23; };

__device__ __forceinline__ EdgeVals unpack_bm(uint4 raw) {
    EdgeVals ev;
    const __half2* hp = (const __half2*)&raw;
    ev.b01 = __half22float2(hp[0]);
    ev.b23 = __half22float2(hp[1]);
    ev.m01 = __half22float2(hp[2]);
    ev.m23 = __half22float2(hp[3]);
    return ev;
}

__global__ __launch_bounds__(256) void fused_aggr_kernel(
    const float* __restrict__ attn_bin,   // [10, 8]
    const float* __restrict__ attn_vec,   // [128]
    float* __restrict__ out,
    int M)
{
    __shared__ float lbin[16 * NUM_HEAD];
    if (threadIdx.x < 10 * NUM_HEAD)
        lbin[threadIdx.x] = leaky(attn_bin[threadIdx.x]);
    __syncthreads();

    int warp = blockIdx.x * (blockDim.x >> 5) + (threadIdx.x >> 5);
    int lane = threadIdx.x & 31;
    if (warp >= M) return;
    int h = warp;

    int e0 = g_off[h];
    int e1 = g_off[h + 1];

    float4 a = *(const float4*)(g_A + (long)h * DIM + lane * 4);
    float4 v = *(const float4*)(attn_vec + lane * 4);
    int k = lane >> 2;

    const uint4* BMv = (const uint4*)g_BM;

    float4 acc = make_float4(0.f, 0.f, 0.f, 0.f);
    float ssum = 0.f;

    unsigned int r0 = 0, r1 = 0, r2 = 0, r3 = 0;
    int n = e1 - e0;
    if (n > 0) r0 = __ldg(g_rec + e0);
    if (n > 1) r1 = __ldg(g_rec + e0 + 1);
    if (n > 2) r2 = __ldg(g_rec + e0 + 2);
    if (n > 3) r3 = __ldg(g_rec + e0 + 3);

    int e = e0;
    while (e + 3 < e1) {
        int t0 = r0 & 0xFFFFu, b0 = r0 >> 16;
        int t1 = r1 & 0xFFFFu, b1 = r1 >> 16;
        int t2 = r2 & 0xFFFFu, b2 = r2 >> 16;
        int t3 = r3 & 0xFFFFu, b3 = r3 >> 16;
        if (e + 4 < e1) r0 = __ldg(g_rec + e + 4);
        if (e + 5 < e1) r1 = __ldg(g_rec + e + 5);
        if (e + 6 < e1) r2 = __ldg(g_rec + e + 6);
        if (e + 7 < e1) r3 = __ldg(g_rec + e + 7);

        uint4 raw0 = BMv[(size_t)t0 * 32 + lane];
        uint4 raw1 = BMv[(size_t)t1 * 32 + lane];
        uint4 raw2 = BMv[(size_t)t2 * 32 + lane];
        uint4 raw3 = BMv[(size_t)t3 * 32 + lane];
        float lb0 = lbin[b0 * NUM_HEAD + k];
        float lb1 = lbin[b1 * NUM_HEAD + k];
        float lb2 = lbin[b2 * NUM_HEAD + k];
        float lb3 = lbin[b3 * NUM_HEAD + k];

        EdgeVals ev0 = unpack_bm(raw0);
        EdgeVals ev1 = unpack_bm(raw1);
        EdgeVals ev2 = unpack_bm(raw2);
        EdgeVals ev3 = unpack_bm(raw3);

        float s0 = leaky(a.x + ev0.b01.x) * v.x + leaky(a.y + ev0.b01.y) * v.y
                 + leaky(a.z + ev0.b23.x) * v.z + leaky(a.w + ev0.b23.y) * v.w;
        float s1 = leaky(a.x + ev1.b01.x) * v.x + leaky(a.y + ev1.b01.y) * v.y
                 + leaky(a.z + ev1.b23.x) * v.z + leaky(a.w + ev1.b23.y) * v.w;
        float s2 = leaky(a.x + ev2.b01.x) * v.x + leaky(a.y + ev2.b01.y) * v.y
                 + leaky(a.z + ev2.b23.x) * v.z + leaky(a.w + ev2.b23.y) * v.w;
        float s3 = leaky(a.x + ev3.b01.x) * v.x + leaky(a.y + ev3.b01.y) * v.y
                 + leaky(a.z + ev3.b23.x) * v.z + leaky(a.w + ev3.b23.y) * v.w;

        float q0 = __shfl_xor_sync(0xFFFFFFFFu, s0, 1);
        float q1 = __shfl_xor_sync(0xFFFFFFFFu, s1, 1);
        float q2 = __shfl_xor_sync(0xFFFFFFFFu, s2, 1);
        float q3 = __shfl_xor_sync(0xFFFFFFFFu, s3, 1);
        s0 += q0; s1 += q1; s2 += q2; s3 += q3;
        q0 = __shfl_xor_sync(0xFFFFFFFFu, s0, 2);
        q1 = __shfl_xor_sync(0xFFFFFFFFu, s1, 2);
        q2 = __shfl_xor_sync(0xFFFFFFFFu, s2, 2);
        q3 = __shfl_xor_sync(0xFFFFFFFFu, s3, 2);
        s0 += q0; s1 += q1; s2 += q2; s3 += q3;

        float val0 = __expf(s0 + lb0);
        float val1 = __expf(s1 + lb1);
        float val2 = __expf(s2 + lb2);
        float val3 = __expf(s3 + lb3);

        acc.x += val0 * ev0.m01.x; acc.y += val0 * ev0.m01.y;
        acc.z += val0 * ev0.m23.x; acc.w += val0 * ev0.m23.y; ssum += val0;
        acc.x += val1 * ev1.m01.x; acc.y += val1 * ev1.m01.y;
        acc.z += val1 * ev1.m23.x; acc.w += val1 * ev1.m23.y; ssum += val1;
        acc.x += val2 * ev2.m01.x; acc.y += val2 * ev2.m01.y;
        acc.z += val2 * ev2.m23.x; acc.w += val2 * ev2.m23.y; ssum += val2;
        acc.x += val3 * ev3.m01.x; acc.y += val3 * ev3.m01.y;
        acc.z += val3 * ev3.m23.x; acc.w += val3 * ev3.m23.y; ssum += val3;

        e += 4;
    }

    for (; e < e1; e++) {
        unsigned int rec = __ldg(g_rec + e);
        int t = rec & 0xFFFFu, b = rec >> 16;
        uint4 raw = BMv[(size_t)t * 32 + lane];
        EdgeVals ev = unpack_bm(raw);

        float s = leaky(a.x + ev.b01.x) * v.x + leaky(a.y + ev.b01.y) * v.y
                + leaky(a.z + ev.b23.x) * v.z + leaky(a.w + ev.b23.y) * v.w;
        s += __shfl_xor_sync(0xFFFFFFFFu, s, 1);
        s += __shfl_xor_sync(0xFFFFFFFFu, s, 2);

        float val = __expf(s + lbin[b * NUM_HEAD + k]);
        acc.x += val * ev.m01.x; acc.y += val * ev.m01.y;
        acc.z += val * ev.m23.x; acc.w += val * ev.m23.y; ssum += val;
    }

    float inv = __frcp_rn(ssum + 1e-16f);
    *(float4*)(out + (long)h * DIM + lane * 4) =
        make_float4(acc.x * inv, acc.y * inv, acc.z * inv, acc.w * inv);
}

// ---------------------------------------------------------------------------
extern "C" void kernel_launch(void* const* d_in, const int* in_sizes, int n_in,
                              void* d_out, int out_size)
{
    const float* emb      = (const float*)d_in[0];
    const void*  trip     = (const void*)d_in[1];
    const float* attn_w   = (const float*)d_in[2];
    const float* attn_b   = (const float*)d_in[3];
    const float* attn_bin = (const float*)d_in[4];
    const float* attn_vec = (const float*)d_in[5];
    const float* aggr_w   = (const float*)d_in[6];
    const float* aggr_b   = (const float*)d_in[7];
    float*       out      = (float*)d_out;

    int M = in_sizes[0] / DIM;        // 20000
    int E = in_sizes[1] / 3;          // 640000
    int nblk = (M + SCAN_B - 1) / SCAN_B;

    static cudaStream_t s_gemm = nullptr;
    static cudaEvent_t ev_fork = nullptr, ev_join = nullptr;
    if (s_gemm == nullptr) {
        cudaStreamCreateWithFlags(&s_gemm, cudaStreamNonBlocking);
        cudaEventCreateWithFlags(&ev_fork, cudaEventDisableTiming);
        cudaEventCreateWithFlags(&ev_join, cudaEventDisableTiming);
    }

    // Fork: hi/lo conversion + HMMA GEMM on the side stream.
    cudaEventRecord(ev_fork, 0);
    cudaStreamWaitEvent(s_gemm, ev_fork, 0);

    conv_emb_kernel<<<592, 256, 0, s_gemm>>>(emb, M * DIM);
    conv_w_kernel<<<(384 * DIM + 255) / 256, 256, 0, s_gemm>>>(attn_w, aggr_w);
    dim3 ggrid((M + GBM - 1) / GBM, 6);
    gemm_hmma_kernel<<<ggrid, 256, 0, s_gemm>>>(attn_b, aggr_b, M);
    cudaEventRecord(ev_join, s_gemm);

    // Main stream: counting sort by head.
    detect_zero_kernel<<<80, 256>>>((const unsigned int*)trip, E * 3, M);
    hist_kernel<<<592, 256>>>(trip, E);
    scan1_kernel<<<nblk, SCAN_B>>>(M);
    scan2_kernel<<<1, 32>>>(nblk, M);
    scan3_kernel<<<nblk, SCAN_B>>>(M);
    reorder_kernel<<<592, 256>>>(trip, E);

    // Join: fused aggregation needs tables + sorted edges.
    cudaStreamWaitEvent(0, ev_join, 0);

    int warps_per_block = 256 / 32;
    int nblocks = (M + warps_per_block - 1) / warps_per_block;
    fused_aggr_kernel<<<nblocks, 256>>>(attn_bin, attn_vec, out, M);
}